// round 5
// baseline (speedup 1.0000x reference)
#include <cuda_runtime.h>
#include <cuda_bf16.h>
#include <cstdint>

#define HWSZ 65536
#define DDIM 1536
#define TOKB_PART (64u*256u*1536u)

__device__ float g_qkv[8u*144u*65536u];
__device__ __nv_bfloat16 g_tokb[3u*TOKB_PART];   // q,k,v(hi) bf16 [part][bh][tok][d]
__device__ __nv_bfloat16 g_vlo[TOKB_PART];       // v residual
__device__ float g_rnorm[2u*16384u];
__device__ float g_oimg[8u*48u*65536u];

__device__ __forceinline__ uint32_t smem_u32(const void* p) {
    uint32_t a;
    asm("{ .reg .u64 t; cvta.to.shared.u64 t, %1; cvt.u32.u64 %0, t; }" : "=r"(a) : "l"(p));
    return a;
}
#define SW128(o) ((o) ^ (((o) >> 3) & 0x70))

__device__ __forceinline__ void ldsm_x4(uint32_t* r, uint32_t a) {
    asm volatile("ldmatrix.sync.aligned.m8n8.x4.shared.b16 {%0,%1,%2,%3}, [%4];"
                 : "=r"(r[0]), "=r"(r[1]), "=r"(r[2]), "=r"(r[3]) : "r"(a));
}
__device__ __forceinline__ void ldsm_x2(uint32_t* r, uint32_t a) {
    asm volatile("ldmatrix.sync.aligned.m8n8.x2.shared.b16 {%0,%1}, [%2];"
                 : "=r"(r[0]), "=r"(r[1]) : "r"(a));
}
__device__ __forceinline__ void ldsm_x2t(uint32_t* r, uint32_t a) {
    asm volatile("ldmatrix.sync.aligned.m8n8.x2.trans.shared.b16 {%0,%1}, [%2];"
                 : "=r"(r[0]), "=r"(r[1]) : "r"(a));
}
__device__ __forceinline__ void mma_bf16(float* c, const uint32_t* a, const uint32_t* b) {
    asm volatile(
        "mma.sync.aligned.m16n8k16.row.col.f32.bf16.bf16.f32 "
        "{%0,%1,%2,%3}, {%4,%5,%6,%7}, {%8,%9}, {%0,%1,%2,%3};"
        : "+f"(c[0]), "+f"(c[1]), "+f"(c[2]), "+f"(c[3])
        : "r"(a[0]), "r"(a[1]), "r"(a[2]), "r"(a[3]), "r"(b[0]), "r"(b[1]));
}
__device__ __forceinline__ void split_hl(float v, __nv_bfloat16& h, __nv_bfloat16& l) {
    h = __float2bfloat16(v);
    l = __float2bfloat16(v - __bfloat162float(h));
}

// ---------------------------------------------------------------------------
// K1: qkv 1x1 conv via hi/lo bf16 HMMA. Block: 256 px x 144 outputs.
// M=256 px (A, row-major K), N=144 outs (B, K-major), K=48 pad 64.
// Warps 4m x 2n: warp tile 64 px x 72 outs (9 n-frags, 4 m-frags).
// smem: Xhi 32K | Xlo 32K | Whi 18K | Wlo 18K ; stage (72x260 f32) overlays.
// ---------------------------------------------------------------------------
__global__ __launch_bounds__(256) void k_qkv(const float* __restrict__ x,
                                             const float* __restrict__ wq) {
    extern __shared__ __align__(128) char smq[];
    char* Xhi = smq;
    char* Xlo = smq + 32768;
    char* Whi = smq + 65536;
    char* Wlo = smq + 83968;
    float* stg = (float*)smq;

    const int t = threadIdx.x;
    const int warp = t >> 5, lane = t & 31, lm = lane & 15;
    const int b = blockIdx.y;
    const int p0 = blockIdx.x * 256;

    // W -> smem hi/lo, K padded to 64 (zeros)
    for (int i = t; i < 144 * 64; i += 256) {
        int o = i >> 6, c = i & 63;
        float w = (c < 48) ? wq[o * 48 + c] : 0.f;
        __nv_bfloat16 h, l; split_hl(w, h, l);
        *(__nv_bfloat16*)(Whi + SW128(o * 128 + c * 2)) = h;
        *(__nv_bfloat16*)(Wlo + SW128(o * 128 + c * 2)) = l;
    }
    // X -> smem transposed [px][c] hi/lo
    const float* xb = x + (size_t)b * 48 * HWSZ + p0;
#pragma unroll 1
    for (int c = 0; c < 48; c++) {
        float v = xb[(size_t)c * HWSZ + t];
        __nv_bfloat16 h, l; split_hl(v, h, l);
        *(__nv_bfloat16*)(Xhi + SW128(t * 128 + c * 2)) = h;
        *(__nv_bfloat16*)(Xlo + SW128(t * 128 + c * 2)) = l;
    }
#pragma unroll
    for (int c = 48; c < 64; c++) {
        *(__nv_bfloat16*)(Xhi + SW128(t * 128 + c * 2)) = __float2bfloat16(0.f);
        *(__nv_bfloat16*)(Xlo + SW128(t * 128 + c * 2)) = __float2bfloat16(0.f);
    }
    __syncthreads();

    const int warpM = warp >> 1, warpN = warp & 1;
    const int m0 = warpM * 64, n0 = warpN * 72;
    const uint32_t aXh = smem_u32(Xhi), aXl = smem_u32(Xlo);
    const uint32_t aWh = smem_u32(Whi), aWl = smem_u32(Wlo);

    float acc[4][9][4];
#pragma unroll
    for (int i = 0; i < 4; i++)
#pragma unroll
        for (int j = 0; j < 9; j++)
#pragma unroll
            for (int q = 0; q < 4; q++) acc[i][j][q] = 0.f;

#pragma unroll
    for (int ks = 0; ks < 4; ks++) {
        int k0 = ks * 16;
        uint32_t ah[4][4], al[4][4];
#pragma unroll
        for (int i = 0; i < 4; i++) {
            int row = m0 + i * 16 + lm;
            ldsm_x4(ah[i], aXh + SW128(row * 128 + k0 * 2 + ((lane >> 4) << 4)));
            ldsm_x4(al[i], aXl + SW128(row * 128 + k0 * 2 + ((lane >> 4) << 4)));
        }
        uint32_t bh2[9][2], bl2[9][2];
#pragma unroll
        for (int j = 0; j < 9; j++) {
            int row = n0 + j * 8 + (lm & 7);
            ldsm_x2(bh2[j], aWh + SW128(row * 128 + (k0 + ((lm >> 3) << 3)) * 2));
            ldsm_x2(bl2[j], aWl + SW128(row * 128 + (k0 + ((lm >> 3) << 3)) * 2));
        }
#pragma unroll
        for (int i = 0; i < 4; i++)
#pragma unroll
            for (int j = 0; j < 9; j++) {
                mma_bf16(acc[i][j], ah[i], bh2[j]);
                mma_bf16(acc[i][j], ah[i], bl2[j]);
                mma_bf16(acc[i][j], al[i], bh2[j]);
            }
    }
    __syncthreads();

    float* outb = g_qkv + (size_t)b * 144 * HWSZ + p0;
#pragma unroll 1
    for (int round = 0; round < 2; round++) {
        if (warpN == round) {
#pragma unroll
            for (int i = 0; i < 4; i++) {
                int px0 = m0 + i * 16 + (lane >> 2);
#pragma unroll
                for (int j = 0; j < 9; j++) {
                    int ol = j * 8 + ((lane & 3) << 1);
                    stg[ol * 260 + px0]             = acc[i][j][0];
                    stg[(ol + 1) * 260 + px0]       = acc[i][j][1];
                    stg[ol * 260 + px0 + 8]         = acc[i][j][2];
                    stg[(ol + 1) * 260 + px0 + 8]   = acc[i][j][3];
                }
            }
        }
        __syncthreads();
#pragma unroll 1
        for (int i = 0; i < 72; i++)
            outb[(size_t)(round * 72 + i) * HWSZ + t] = stg[i * 260 + t];
        __syncthreads();
    }
}

// ---------------------------------------------------------------------------
// K2: depthwise 3x3, single pass per (ch,b); 18-row groups -> bf16 tokens
// ---------------------------------------------------------------------------
__global__ __launch_bounds__(256) void k_dw(const float* __restrict__ wdw) {
    __shared__ float rows[18][260];
    __shared__ float s2[256 * 17];
    const int t = threadIdx.x;
    const int ch = blockIdx.x, b = blockIdx.y;
    const float* src = g_qkv + ((size_t)(b * 144 + ch)) * HWSZ;

    float wd[9];
#pragma unroll
    for (int j = 0; j < 9; j++) wd[j] = wdw[ch * 9 + j];

    const int part = ch / 48, cc = ch % 48;
    const int head = cc / 6, c = cc % 6;
    const size_t base = (size_t)part * TOKB_PART +
                        ((size_t)((b * 8 + head) * 256)) * DDIM + c * 256;
    const size_t vbase = ((size_t)((b * 8 + head) * 256)) * DDIM + c * 256;

#pragma unroll 1
    for (int g = 0; g < 16; g++) {
        int y0 = g * 16;
#pragma unroll
        for (int r = 0; r < 18; r++) {
            int y = y0 - 1 + r;
            rows[r][t] = ((unsigned)y < 256u) ? src[y * 256 + t] : 0.f;
        }
        __syncthreads();
#pragma unroll 1
        for (int k = 0; k < 16; k++) {
            float v = 0.f;
#pragma unroll
            for (int dy = 0; dy < 3; dy++) {
                const float* rr = rows[k + dy];
                if (t > 0)   v += wd[dy * 3 + 0] * rr[t - 1];
                v += wd[dy * 3 + 1] * rr[t];
                if (t < 255) v += wd[dy * 3 + 2] * rr[t + 1];
            }
            s2[((t & 15) * 16 + k) * 17 + (t >> 4)] = v;
        }
        __syncthreads();
        // flush: thread t = token n, d-slice [c*256 + g*16, +16)
        {
            __nv_bfloat16 hb[16], lb[16];
#pragma unroll
            for (int ww = 0; ww < 16; ww++) {
                float v = s2[t * 17 + ww];
                split_hl(v, hb[ww], lb[ww]);
            }
            uint4* dst = (uint4*)(&g_tokb[base + (size_t)t * DDIM + g * 16]);
            dst[0] = ((uint4*)hb)[0];
            dst[1] = ((uint4*)hb)[1];
            if (part == 2) {
                uint4* dlo = (uint4*)(&g_vlo[vbase + (size_t)t * DDIM + g * 16]);
                dlo[0] = ((uint4*)lb)[0];
                dlo[1] = ((uint4*)lb)[1];
            }
        }
        __syncthreads();
    }
}

// ---------------------------------------------------------------------------
// K2b: reciprocal L2 norms
// ---------------------------------------------------------------------------
__global__ __launch_bounds__(256) void k_norm() {
    int t = threadIdx.x;
    int w = t >> 5, lane = t & 31;
    int rid = blockIdx.x * 8 + w;
    const __nv_bfloat16* p = g_tokb + (size_t)rid * DDIM;
    float ss = 0.f;
#pragma unroll
    for (int i = 0; i < 48; i++) {
        float v = __bfloat162float(p[lane + 32 * i]);
        ss += v * v;
    }
#pragma unroll
    for (int off = 16; off; off >>= 1) ss += __shfl_xor_sync(0xffffffffu, ss, off);
    if (lane == 0) g_rnorm[rid] = 1.0f / fmaxf(sqrtf(ss), 1e-12f);
}

// ---------------------------------------------------------------------------
// K3: attention (unchanged from R4)
// ---------------------------------------------------------------------------
__global__ __launch_bounds__(256, 1) void k_attn(const float* __restrict__ temperature) {
    extern __shared__ __align__(128) char sm[];
    char* Ahi = sm;
    char* Alo = sm + 67584;
    char* Tc  = sm + 135168;
    float* rqs  = (float*)(sm + 200704);
    float* rks  = rqs + 128;
    float* rsp  = rks + 256;
    float* rsum = rsp + 512;

    const int t = threadIdx.x;
    const int warp = t >> 5, lane = t & 31;
    const int mt = blockIdx.x;
    const int bh = blockIdx.y;
    const int head = bh & 7;
    const int b = bh >> 3;

    const __nv_bfloat16* gq = g_tokb + (size_t)bh * 256 * DDIM;
    const __nv_bfloat16* gk = g_tokb + (size_t)TOKB_PART + (size_t)bh * 256 * DDIM;
    const __nv_bfloat16* gv = g_tokb + 2u * (size_t)TOKB_PART + (size_t)bh * 256 * DDIM;
    const __nv_bfloat16* gvl = g_vlo + (size_t)bh * 256 * DDIM;

    const uint32_t aAh = smem_u32(Ahi);
    const uint32_t aAl = smem_u32(Alo);
    const uint32_t aV  = smem_u32(Tc);
    const uint32_t aK  = aV + 16384;
    const uint32_t aVl = aV + 32768;

    if (t < 128) {
        int n = (t >> 3) * 16 + mt * 8 + (t & 7);
        rqs[t] = g_rnorm[bh * 256 + n] * temperature[head];
    }
    rks[t] = g_rnorm[16384 + bh * 256 + t];

    const int warpM = warp >> 2, warpN = warp & 3;
    float acc[4][8][4];
#pragma unroll
    for (int i = 0; i < 4; i++)
#pragma unroll
        for (int j = 0; j < 8; j++)
#pragma unroll
            for (int q = 0; q < 4; q++) acc[i][j][q] = 0.f;

#pragma unroll 1
    for (int ck = 0; ck < 24; ck++) {
        int d0 = ck * 64;
#pragma unroll
        for (int i = 0; i < 4; i++) {
            int s = t + 256 * i; int r = s >> 3, cs = s & 7;
            int n = (r >> 3) * 16 + mt * 8 + (r & 7);
            uint4 v = *(const uint4*)(gq + (size_t)n * DDIM + d0 + cs * 8);
            *(uint4*)(Tc + SW128(r * 128 + cs * 16)) = v;
        }
#pragma unroll
        for (int i = 0; i < 8; i++) {
            int s = t + 256 * i; int m2 = s >> 3, cs = s & 7;
            uint4 v = *(const uint4*)(gk + (size_t)m2 * DDIM + d0 + cs * 8);
            *(uint4*)(Tc + 16384 + SW128(m2 * 128 + cs * 16)) = v;
        }
        __syncthreads();

        int lm = lane & 15;
#pragma unroll
        for (int kk = 0; kk < 4; kk++) {
            int k0 = kk * 16;
            uint32_t af[4][4];
#pragma unroll
            for (int i = 0; i < 4; i++) {
                int row = warpM * 64 + i * 16 + lm;
                ldsm_x4(af[i], aV + SW128(row * 128 + k0 * 2 + ((lane >> 4) << 4)));
            }
            uint32_t bfg[8][2];
#pragma unroll
            for (int j = 0; j < 8; j++) {
                int row = warpN * 64 + j * 8 + (lm & 7);
                ldsm_x2(bfg[j], aK + SW128(row * 128 + (k0 + ((lm >> 3) << 3)) * 2));
            }
#pragma unroll
            for (int i = 0; i < 4; i++)
#pragma unroll
                for (int j = 0; j < 8; j++) mma_bf16(acc[i][j], af[i], bfg[j]);
        }
        __syncthreads();
    }

#pragma unroll
    for (int i = 0; i < 4; i++) {
        int m0 = warpM * 64 + i * 16 + (lane >> 2);
        int m1 = m0 + 8;
        float q0 = rqs[m0], q1 = rqs[m1];
        float r0 = 0.f, r1 = 0.f;
#pragma unroll
        for (int j = 0; j < 8; j++) {
            int n0 = warpN * 64 + j * 8 + ((lane & 3) << 1);
            float k0v = rks[n0], k1v = rks[n0 + 1];
            float e00 = __expf(acc[i][j][0] * q0 * k0v);
            float e01 = __expf(acc[i][j][1] * q0 * k1v);
            float e10 = __expf(acc[i][j][2] * q1 * k0v);
            float e11 = __expf(acc[i][j][3] * q1 * k1v);
            r0 += e00 + e01; r1 += e10 + e11;
            uint32_t p0, p1;
            asm("cvt.rn.bf16x2.f32 %0, %1, %2;" : "=r"(p0) : "f"(e01), "f"(e00));
            asm("cvt.rn.bf16x2.f32 %0, %1, %2;" : "=r"(p1) : "f"(e11), "f"(e10));
            float h00 = __uint_as_float(p0 << 16),  h01 = __uint_as_float(p0 & 0xFFFF0000u);
            float h10 = __uint_as_float(p1 << 16),  h11 = __uint_as_float(p1 & 0xFFFF0000u);
            uint32_t q0p, q1p;
            asm("cvt.rn.bf16x2.f32 %0, %1, %2;" : "=r"(q0p) : "f"(e01 - h01), "f"(e00 - h00));
            asm("cvt.rn.bf16x2.f32 %0, %1, %2;" : "=r"(q1p) : "f"(e11 - h11), "f"(e10 - h10));
            *(uint32_t*)(Ahi + m0 * 528 + n0 * 2) = p0;
            *(uint32_t*)(Ahi + m1 * 528 + n0 * 2) = p1;
            *(uint32_t*)(Alo + m0 * 528 + n0 * 2) = q0p;
            *(uint32_t*)(Alo + m1 * 528 + n0 * 2) = q1p;
        }
        r0 += __shfl_xor_sync(0xffffffffu, r0, 1);
        r0 += __shfl_xor_sync(0xffffffffu, r0, 2);
        r1 += __shfl_xor_sync(0xffffffffu, r1, 1);
        r1 += __shfl_xor_sync(0xffffffffu, r1, 2);
        if ((lane & 3) == 0) {
            rsp[warpN * 128 + m0] = r0;
            rsp[warpN * 128 + m1] = r1;
        }
    }
    __syncthreads();
    if (t < 128) rsum[t] = 1.0f / (rsp[t] + rsp[128 + t] + rsp[256 + t] + rsp[384 + t] + 1.0f);
    __syncthreads();

    float* oimg_base = g_oimg + ((size_t)(b * 48 + head * 6)) * HWSZ;
    const int fy0 = mt * 8;
    const int lm = lane & 15;
#pragma unroll 1
    for (int ck = 0; ck < 24; ck++) {
        int d0 = ck * 64;
#pragma unroll
        for (int i = 0; i < 8; i++) {
            int s = t + 256 * i; int m2 = s >> 3, cs = s & 7;
            uint4 v = *(const uint4*)(gv + (size_t)m2 * DDIM + d0 + cs * 8);
            *(uint4*)(Tc + SW128(m2 * 128 + cs * 16)) = v;
            uint4 vl = *(const uint4*)(gvl + (size_t)m2 * DDIM + d0 + cs * 8);
            *(uint4*)(Tc + 32768 + SW128(m2 * 128 + cs * 16)) = vl;
        }
        __syncthreads();

        float oacc[8][4];
#pragma unroll
        for (int j = 0; j < 8; j++)
#pragma unroll
            for (int q = 0; q < 4; q++) oacc[j][q] = 0.f;

        int m0r = warp * 16;
#pragma unroll 1
        for (int kk = 0; kk < 16; kk++) {
            int n0 = kk * 16;
            uint32_t afh[4], afl[4];
            ldsm_x4(afh, aAh + (m0r + lm) * 528 + (n0 + ((lane >> 4) << 3)) * 2);
            ldsm_x4(afl, aAl + (m0r + lm) * 528 + (n0 + ((lane >> 4) << 3)) * 2);
#pragma unroll
            for (int j = 0; j < 8; j++) {
                uint32_t bh2[2], bl2[2];
                ldsm_x2t(bh2, aV + SW128((n0 + lm) * 128 + j * 16));
                ldsm_x2t(bl2, aVl + SW128((n0 + lm) * 128 + j * 16));
                mma_bf16(oacc[j], afh, bh2);
                mma_bf16(oacc[j], afh, bl2);
                mma_bf16(oacc[j], afl, bh2);
            }
        }
        __syncthreads();

        float* stg = (float*)Tc;
        int r0 = m0r + (lane >> 2), r1 = r0 + 8;
        float s0 = rsum[r0], s1 = rsum[r1];
        int fx0 = r0 >> 3, fyl0 = r0 & 7;
        int fx1 = r1 >> 3, fyl1 = r1 & 7;
#pragma unroll
        for (int j = 0; j < 8; j++) {
            int cd = j * 8 + ((lane & 3) << 1);
            int hl = cd >> 4, ww = cd & 15;
            stg[(hl * 8 + fyl0) * 260 + ww * 16 + fx0]       = oacc[j][0] * s0;
            stg[(hl * 8 + fyl0) * 260 + (ww + 1) * 16 + fx0] = oacc[j][1] * s0;
            stg[(hl * 8 + fyl1) * 260 + ww * 16 + fx1]       = oacc[j][2] * s1;
            stg[(hl * 8 + fyl1) * 260 + (ww + 1) * 16 + fx1] = oacc[j][3] * s1;
        }
        __syncthreads();
        int c = ck >> 2, hh0 = (ck & 3) * 4;
#pragma unroll
        for (int rr = 0; rr < 32; rr++) {
            int y = (hh0 + (rr >> 3)) * 16 + fy0 + (rr & 7);
            oimg_base[((size_t)c * 256 + y) * 256 + t] = stg[rr * 260 + t];
        }
        __syncthreads();
    }
}

// ---------------------------------------------------------------------------
// K4: project_out via hi/lo bf16 HMMA. 256 px x 48 outs, K=48 pad 64.
// Warps 4m x 2n: warp = 64 px x 24 outs (3 n-frags).
// ---------------------------------------------------------------------------
__global__ __launch_bounds__(256) void k_proj(const float* __restrict__ wp,
                                              float* __restrict__ out) {
    extern __shared__ __align__(128) char smp[];
    char* Xhi = smp;
    char* Xlo = smp + 32768;
    char* Whi = smp + 65536;
    char* Wlo = smp + 71680;
    float* stg = (float*)smp;

    const int t = threadIdx.x;
    const int warp = t >> 5, lane = t & 31, lm = lane & 15;
    const int b = blockIdx.y;
    const int p0 = blockIdx.x * 256;

    for (int i = t; i < 48 * 64; i += 256) {
        int o = i >> 6, c = i & 63;
        float w = (c < 48) ? wp[o * 48 + c] : 0.f;
        __nv_bfloat16 h, l; split_hl(w, h, l);
        *(__nv_bfloat16*)(Whi + SW128(o * 128 + c * 2)) = h;
        *(__nv_bfloat16*)(Wlo + SW128(o * 128 + c * 2)) = l;
    }
    const float* xb = g_oimg + (size_t)b * 48 * HWSZ + p0;
#pragma unroll 1
    for (int c = 0; c < 48; c++) {
        float v = xb[(size_t)c * HWSZ + t];
        __nv_bfloat16 h, l; split_hl(v, h, l);
        *(__nv_bfloat16*)(Xhi + SW128(t * 128 + c * 2)) = h;
        *(__nv_bfloat16*)(Xlo + SW128(t * 128 + c * 2)) = l;
    }
#pragma unroll
    for (int c = 48; c < 64; c++) {
        *(__nv_bfloat16*)(Xhi + SW128(t * 128 + c * 2)) = __float2bfloat16(0.f);
        *(__nv_bfloat16*)(Xlo + SW128(t * 128 + c * 2)) = __float2bfloat16(0.f);
    }
    __syncthreads();

    const int warpM = warp >> 1, warpN = warp & 1;
    const int m0 = warpM * 64, n0 = warpN * 24;
    const uint32_t aXh = smem_u32(Xhi), aXl = smem_u32(Xlo);
    const uint32_t aWh = smem_u32(Whi), aWl = smem_u32(Wlo);

    float acc[4][3][4];
#pragma unroll
    for (int i = 0; i < 4; i++)
#pragma unroll
        for (int j = 0; j < 3; j++)
#pragma unroll
            for (int q = 0; q < 4; q++) acc[i][j][q] = 0.f;

#pragma unroll
    for (int ks = 0; ks < 4; ks++) {
        int k0 = ks * 16;
        uint32_t ah[4][4], al[4][4];
#pragma unroll
        for (int i = 0; i < 4; i++) {
            int row = m0 + i * 16 + lm;
            ldsm_x4(ah[i], aXh + SW128(row * 128 + k0 * 2 + ((lane >> 4) << 4)));
            ldsm_x4(al[i], aXl + SW128(row * 128 + k0 * 2 + ((lane >> 4) << 4)));
        }
        uint32_t bh2[3][2], bl2[3][2];
#pragma unroll
        for (int j = 0; j < 3; j++) {
            int row = n0 + j * 8 + (lm & 7);
            ldsm_x2(bh2[j], aWh + SW128(row * 128 + (k0 + ((lm >> 3) << 3)) * 2));
            ldsm_x2(bl2[j], aWl + SW128(row * 128 + (k0 + ((lm >> 3) << 3)) * 2));
        }
#pragma unroll
        for (int i = 0; i < 4; i++)
#pragma unroll
            for (int j = 0; j < 3; j++) {
                mma_bf16(acc[i][j], ah[i], bh2[j]);
                mma_bf16(acc[i][j], ah[i], bl2[j]);
                mma_bf16(acc[i][j], al[i], bh2[j]);
            }
    }
    __syncthreads();

#pragma unroll
    for (int i = 0; i < 4; i++) {
        int px0 = m0 + i * 16 + (lane >> 2);
#pragma unroll
        for (int j = 0; j < 3; j++) {
            int ol = n0 + j * 8 + ((lane & 3) << 1);
            stg[ol * 260 + px0]           = acc[i][j][0];
            stg[(ol + 1) * 260 + px0]     = acc[i][j][1];
            stg[ol * 260 + px0 + 8]       = acc[i][j][2];
            stg[(ol + 1) * 260 + px0 + 8] = acc[i][j][3];
        }
    }
    __syncthreads();
    float* ob = out + (size_t)b * 48 * HWSZ + p0;
#pragma unroll 1
    for (int i = 0; i < 48; i++)
        ob[(size_t)i * HWSZ + t] = stg[i * 260 + t];
}

extern "C" void kernel_launch(void* const* d_in, const int* in_sizes, int n_in,
                              void* d_out, int out_size) {
    const float* x      = (const float*)d_in[0];
    const float* w_qkv  = (const float*)d_in[1];
    const float* w_dw   = (const float*)d_in[2];
    const float* w_proj = (const float*)d_in[3];
    const float* temp   = (const float*)d_in[4];
    float* out = (float*)d_out;

    cudaFuncSetAttribute(k_attn, cudaFuncAttributeMaxDynamicSharedMemorySize, 208 * 1024);
    cudaFuncSetAttribute(k_qkv, cudaFuncAttributeMaxDynamicSharedMemorySize, 104 * 1024);
    cudaFuncSetAttribute(k_proj, cudaFuncAttributeMaxDynamicSharedMemorySize, 80 * 1024);

    k_qkv<<<dim3(256, 8), 256, 102400>>>(x, w_qkv);
    k_dw<<<dim3(144, 8), 256>>>(w_dw);
    k_norm<<<4096, 256>>>();
    k_attn<<<dim3(2, 64), 256, 204800>>>(temp);
    k_proj<<<dim3(256, 8), 256, 77824>>>(w_proj, out);
}

// round 7
// speedup vs baseline: 1.8391x; 1.8391x over previous
#include <cuda_runtime.h>
#include <cuda_bf16.h>
#include <cstdint>

#define HWSZ 65536
#define DDIM 1536
#define TOKB_PART (64u*256u*1536u)

__device__ float g_qkv[8u*144u*65536u];
__device__ __nv_bfloat16 g_tokb[3u*TOKB_PART];   // q,k,v(hi) bf16 [part][bh][tok][d]
__device__ __nv_bfloat16 g_vlo[TOKB_PART];       // v residual
__device__ float g_rnorm[2u*16384u];
__device__ float g_oimg[8u*48u*65536u];

__device__ __forceinline__ uint32_t smem_u32(const void* p) {
    uint32_t a;
    asm("{ .reg .u64 t; cvta.to.shared.u64 t, %1; cvt.u32.u64 %0, t; }" : "=r"(a) : "l"(p));
    return a;
}
#define SW128(o) ((o) ^ (((o) >> 3) & 0x70))

__device__ __forceinline__ void ldsm_x4(uint32_t* r, uint32_t a) {
    asm volatile("ldmatrix.sync.aligned.m8n8.x4.shared.b16 {%0,%1,%2,%3}, [%4];"
                 : "=r"(r[0]), "=r"(r[1]), "=r"(r[2]), "=r"(r[3]) : "r"(a));
}
__device__ __forceinline__ void ldsm_x2(uint32_t* r, uint32_t a) {
    asm volatile("ldmatrix.sync.aligned.m8n8.x2.shared.b16 {%0,%1}, [%2];"
                 : "=r"(r[0]), "=r"(r[1]) : "r"(a));
}
__device__ __forceinline__ void ldsm_x2t(uint32_t* r, uint32_t a) {
    asm volatile("ldmatrix.sync.aligned.m8n8.x2.trans.shared.b16 {%0,%1}, [%2];"
                 : "=r"(r[0]), "=r"(r[1]) : "r"(a));
}
__device__ __forceinline__ void mma_bf16(float* c, const uint32_t* a, const uint32_t* b) {
    asm volatile(
        "mma.sync.aligned.m16n8k16.row.col.f32.bf16.bf16.f32 "
        "{%0,%1,%2,%3}, {%4,%5,%6,%7}, {%8,%9}, {%0,%1,%2,%3};"
        : "+f"(c[0]), "+f"(c[1]), "+f"(c[2]), "+f"(c[3])
        : "r"(a[0]), "r"(a[1]), "r"(a[2]), "r"(a[3]), "r"(b[0]), "r"(b[1]));
}
__device__ __forceinline__ void split_hl(float v, __nv_bfloat16& h, __nv_bfloat16& l) {
    h = __float2bfloat16(v);
    l = __float2bfloat16(v - __bfloat162float(h));
}

// ---------------------------------------------------------------------------
// K1: qkv 1x1 conv (R4 scalar version)
// ---------------------------------------------------------------------------
__global__ __launch_bounds__(256) void k_qkv(const float* __restrict__ x,
                                             const float* __restrict__ wq) {
    __shared__ float ws[144 * 48];
    __shared__ float xs[48 * 64];
    int t = threadIdx.x;
    int b = blockIdx.y;
    int p0 = blockIdx.x * 64;

    for (int i = t; i < 144 * 48; i += 256) ws[i] = wq[i];
    const float* xb = x + (size_t)b * 48 * HWSZ + p0;
    for (int i = t; i < 48 * 64; i += 256) {
        int c = i >> 6, px = i & 63;
        xs[c * 64 + px] = xb[(size_t)c * HWSZ + px];
    }
    __syncthreads();

    int pxg = t & 15, og = t >> 4;
    float acc[9][4];
#pragma unroll
    for (int j = 0; j < 9; j++)
#pragma unroll
        for (int ii = 0; ii < 4; ii++) acc[j][ii] = 0.f;

#pragma unroll 4
    for (int k = 0; k < 48; k++) {
        float4 xv = *reinterpret_cast<const float4*>(&xs[k * 64 + pxg * 4]);
#pragma unroll
        for (int j = 0; j < 9; j++) {
            float w = ws[(og * 9 + j) * 48 + k];
            acc[j][0] += w * xv.x; acc[j][1] += w * xv.y;
            acc[j][2] += w * xv.z; acc[j][3] += w * xv.w;
        }
    }
    float* outb = g_qkv + (size_t)b * 144 * HWSZ + p0 + pxg * 4;
#pragma unroll
    for (int j = 0; j < 9; j++) {
        int o = og * 9 + j;
        float4 v = make_float4(acc[j][0], acc[j][1], acc[j][2], acc[j][3]);
        *reinterpret_cast<float4*>(&outb[(size_t)o * HWSZ]) = v;
    }
}

// ---------------------------------------------------------------------------
// K2: depthwise 3x3 via smem row cache; thread t = token n.
// Block = (ch, b, z) handles image rows [32z, 32z+32). Input rows 34 in smem
// (pitch 259, col = x+1, zero-padded edges). Thread t: x&15 = t>>4 (fx),
// y&15 = t&15 (fy); computes 2 hl x 16 ww outputs in regs; writes the 32
// contiguous d-values (d = c*256 + (2z+hl)*16 + ww) as bf16 (hi, + lo for V).
// ---------------------------------------------------------------------------
__global__ __launch_bounds__(256) void k_dw(const float* __restrict__ wdw) {
    __shared__ float rows[34 * 259];
    const int t = threadIdx.x;
    const int ch = blockIdx.x, b = blockIdx.y, z = blockIdx.z;
    const float* src = g_qkv + ((size_t)(b * 144 + ch)) * HWSZ;

    float wd[9];
#pragma unroll
    for (int j = 0; j < 9; j++) wd[j] = wdw[ch * 9 + j];

    const int y0 = z * 32;
    for (int idx = t; idx < 34 * 258; idx += 256) {
        int r = idx / 258, col = idx - r * 258;
        int y = y0 - 1 + r, x = col - 1;
        float v = 0.f;
        if ((unsigned)y < 256u && (unsigned)x < 256u) v = src[y * 256 + x];
        rows[r * 259 + col] = v;
    }
    __syncthreads();

    const int fx = t >> 4, fy = t & 15;   // x&15 = fx, y&15 = fy; token n = t
    float ov[2][16];
#pragma unroll
    for (int hl = 0; hl < 2; hl++) {
        const float* r0 = rows + (hl * 16 + fy) * 259 + fx;
        const float* r1 = r0 + 259;
        const float* r2 = r1 + 259;
#pragma unroll
        for (int ww = 0; ww < 16; ww++) {
            int c0 = ww * 16;
            float v = wd[0] * r0[c0] + wd[1] * r0[c0 + 1] + wd[2] * r0[c0 + 2]
                    + wd[3] * r1[c0] + wd[4] * r1[c0 + 1] + wd[5] * r1[c0 + 2]
                    + wd[6] * r2[c0] + wd[7] * r2[c0 + 1] + wd[8] * r2[c0 + 2];
            ov[hl][ww] = v;
        }
    }

    const int part = ch / 48, cc = ch % 48;
    const int head = cc / 6, c = cc % 6;
    const size_t off = (size_t)t * DDIM + c * 256 + z * 32;
    __nv_bfloat16* dst = g_tokb + (size_t)part * TOKB_PART +
                         ((size_t)((b * 8 + head) * 256)) * DDIM + off;
    __nv_bfloat16 hb[32], lb[32];
#pragma unroll
    for (int hl = 0; hl < 2; hl++)
#pragma unroll
        for (int ww = 0; ww < 16; ww++)
            split_hl(ov[hl][ww], hb[hl * 16 + ww], lb[hl * 16 + ww]);
    uint4* d4 = (uint4*)dst;
    d4[0] = ((uint4*)hb)[0]; d4[1] = ((uint4*)hb)[1];
    d4[2] = ((uint4*)hb)[2]; d4[3] = ((uint4*)hb)[3];
    if (part == 2) {
        uint4* l4 = (uint4*)(g_vlo + ((size_t)((b * 8 + head) * 256)) * DDIM + off);
        l4[0] = ((uint4*)lb)[0]; l4[1] = ((uint4*)lb)[1];
        l4[2] = ((uint4*)lb)[2]; l4[3] = ((uint4*)lb)[3];
    }
}

// ---------------------------------------------------------------------------
// K2b: reciprocal L2 norms
// ---------------------------------------------------------------------------
__global__ __launch_bounds__(256) void k_norm() {
    int t = threadIdx.x;
    int w = t >> 5, lane = t & 31;
    int rid = blockIdx.x * 8 + w;
    const __nv_bfloat16* p = g_tokb + (size_t)rid * DDIM;
    float ss = 0.f;
#pragma unroll
    for (int i = 0; i < 48; i++) {
        float v = __bfloat162float(p[lane + 32 * i]);
        ss += v * v;
    }
#pragma unroll
    for (int off = 16; off; off >>= 1) ss += __shfl_xor_sync(0xffffffffu, ss, off);
    if (lane == 0) g_rnorm[rid] = 1.0f / fmaxf(sqrtf(ss), 1e-12f);
}

// ---------------------------------------------------------------------------
// K3: attention (unchanged from R4)
// ---------------------------------------------------------------------------
__global__ __launch_bounds__(256, 1) void k_attn(const float* __restrict__ temperature) {
    extern __shared__ __align__(128) char sm[];
    char* Ahi = sm;
    char* Alo = sm + 67584;
    char* Tc  = sm + 135168;
    float* rqs  = (float*)(sm + 200704);
    float* rks  = rqs + 128;
    float* rsp  = rks + 256;
    float* rsum = rsp + 512;

    const int t = threadIdx.x;
    const int warp = t >> 5, lane = t & 31;
    const int mt = blockIdx.x;
    const int bh = blockIdx.y;
    const int head = bh & 7;
    const int b = bh >> 3;

    const __nv_bfloat16* gq = g_tokb + (size_t)bh * 256 * DDIM;
    const __nv_bfloat16* gk = g_tokb + (size_t)TOKB_PART + (size_t)bh * 256 * DDIM;
    const __nv_bfloat16* gv = g_tokb + 2u * (size_t)TOKB_PART + (size_t)bh * 256 * DDIM;
    const __nv_bfloat16* gvl = g_vlo + (size_t)bh * 256 * DDIM;

    const uint32_t aAh = smem_u32(Ahi);
    const uint32_t aAl = smem_u32(Alo);
    const uint32_t aV  = smem_u32(Tc);
    const uint32_t aK  = aV + 16384;
    const uint32_t aVl = aV + 32768;

    if (t < 128) {
        int n = (t >> 3) * 16 + mt * 8 + (t & 7);
        rqs[t] = g_rnorm[bh * 256 + n] * temperature[head];
    }
    rks[t] = g_rnorm[16384 + bh * 256 + t];

    const int warpM = warp >> 2, warpN = warp & 3;
    float acc[4][8][4];
#pragma unroll
    for (int i = 0; i < 4; i++)
#pragma unroll
        for (int j = 0; j < 8; j++)
#pragma unroll
            for (int q = 0; q < 4; q++) acc[i][j][q] = 0.f;

#pragma unroll 1
    for (int ck = 0; ck < 24; ck++) {
        int d0 = ck * 64;
#pragma unroll
        for (int i = 0; i < 4; i++) {
            int s = t + 256 * i; int r = s >> 3, cs = s & 7;
            int n = (r >> 3) * 16 + mt * 8 + (r & 7);
            uint4 v = *(const uint4*)(gq + (size_t)n * DDIM + d0 + cs * 8);
            *(uint4*)(Tc + SW128(r * 128 + cs * 16)) = v;
        }
#pragma unroll
        for (int i = 0; i < 8; i++) {
            int s = t + 256 * i; int m2 = s >> 3, cs = s & 7;
            uint4 v = *(const uint4*)(gk + (size_t)m2 * DDIM + d0 + cs * 8);
            *(uint4*)(Tc + 16384 + SW128(m2 * 128 + cs * 16)) = v;
        }
        __syncthreads();

        int lm = lane & 15;
#pragma unroll
        for (int kk = 0; kk < 4; kk++) {
            int k0 = kk * 16;
            uint32_t af[4][4];
#pragma unroll
            for (int i = 0; i < 4; i++) {
                int row = warpM * 64 + i * 16 + lm;
                ldsm_x4(af[i], aV + SW128(row * 128 + k0 * 2 + ((lane >> 4) << 4)));
            }
            uint32_t bfg[8][2];
#pragma unroll
            for (int j = 0; j < 8; j++) {
                int row = warpN * 64 + j * 8 + (lm & 7);
                ldsm_x2(bfg[j], aK + SW128(row * 128 + (k0 + ((lm >> 3) << 3)) * 2));
            }
#pragma unroll
            for (int i = 0; i < 4; i++)
#pragma unroll
                for (int j = 0; j < 8; j++) mma_bf16(acc[i][j], af[i], bfg[j]);
        }
        __syncthreads();
    }

#pragma unroll
    for (int i = 0; i < 4; i++) {
        int m0 = warpM * 64 + i * 16 + (lane >> 2);
        int m1 = m0 + 8;
        float q0 = rqs[m0], q1 = rqs[m1];
        float r0 = 0.f, r1 = 0.f;
#pragma unroll
        for (int j = 0; j < 8; j++) {
            int n0 = warpN * 64 + j * 8 + ((lane & 3) << 1);
            float k0v = rks[n0], k1v = rks[n0 + 1];
            float e00 = __expf(acc[i][j][0] * q0 * k0v);
            float e01 = __expf(acc[i][j][1] * q0 * k1v);
            float e10 = __expf(acc[i][j][2] * q1 * k0v);
            float e11 = __expf(acc[i][j][3] * q1 * k1v);
            r0 += e00 + e01; r1 += e10 + e11;
            uint32_t p0, p1;
            asm("cvt.rn.bf16x2.f32 %0, %1, %2;" : "=r"(p0) : "f"(e01), "f"(e00));
            asm("cvt.rn.bf16x2.f32 %0, %1, %2;" : "=r"(p1) : "f"(e11), "f"(e10));
            float h00 = __uint_as_float(p0 << 16),  h01 = __uint_as_float(p0 & 0xFFFF0000u);
            float h10 = __uint_as_float(p1 << 16),  h11 = __uint_as_float(p1 & 0xFFFF0000u);
            uint32_t q0p, q1p;
            asm("cvt.rn.bf16x2.f32 %0, %1, %2;" : "=r"(q0p) : "f"(e01 - h01), "f"(e00 - h00));
            asm("cvt.rn.bf16x2.f32 %0, %1, %2;" : "=r"(q1p) : "f"(e11 - h11), "f"(e10 - h10));
            *(uint32_t*)(Ahi + m0 * 528 + n0 * 2) = p0;
            *(uint32_t*)(Ahi + m1 * 528 + n0 * 2) = p1;
            *(uint32_t*)(Alo + m0 * 528 + n0 * 2) = q0p;
            *(uint32_t*)(Alo + m1 * 528 + n0 * 2) = q1p;
        }
        r0 += __shfl_xor_sync(0xffffffffu, r0, 1);
        r0 += __shfl_xor_sync(0xffffffffu, r0, 2);
        r1 += __shfl_xor_sync(0xffffffffu, r1, 1);
        r1 += __shfl_xor_sync(0xffffffffu, r1, 2);
        if ((lane & 3) == 0) {
            rsp[warpN * 128 + m0] = r0;
            rsp[warpN * 128 + m1] = r1;
        }
    }
    __syncthreads();
    if (t < 128) rsum[t] = 1.0f / (rsp[t] + rsp[128 + t] + rsp[256 + t] + rsp[384 + t] + 1.0f);
    __syncthreads();

    float* oimg_base = g_oimg + ((size_t)(b * 48 + head * 6)) * HWSZ;
    const int fy0 = mt * 8;
    const int lm = lane & 15;
#pragma unroll 1
    for (int ck = 0; ck < 24; ck++) {
        int d0 = ck * 64;
#pragma unroll
        for (int i = 0; i < 8; i++) {
            int s = t + 256 * i; int m2 = s >> 3, cs = s & 7;
            uint4 v = *(const uint4*)(gv + (size_t)m2 * DDIM + d0 + cs * 8);
            *(uint4*)(Tc + SW128(m2 * 128 + cs * 16)) = v;
            uint4 vl = *(const uint4*)(gvl + (size_t)m2 * DDIM + d0 + cs * 8);
            *(uint4*)(Tc + 32768 + SW128(m2 * 128 + cs * 16)) = vl;
        }
        __syncthreads();

        float oacc[8][4];
#pragma unroll
        for (int j = 0; j < 8; j++)
#pragma unroll
            for (int q = 0; q < 4; q++) oacc[j][q] = 0.f;

        int m0r = warp * 16;
#pragma unroll 1
        for (int kk = 0; kk < 16; kk++) {
            int n0 = kk * 16;
            uint32_t afh[4], afl[4];
            ldsm_x4(afh, aAh + (m0r + lm) * 528 + (n0 + ((lane >> 4) << 3)) * 2);
            ldsm_x4(afl, aAl + (m0r + lm) * 528 + (n0 + ((lane >> 4) << 3)) * 2);
#pragma unroll
            for (int j = 0; j < 8; j++) {
                uint32_t bh2[2], bl2[2];
                ldsm_x2t(bh2, aV + SW128((n0 + lm) * 128 + j * 16));
                ldsm_x2t(bl2, aVl + SW128((n0 + lm) * 128 + j * 16));
                mma_bf16(oacc[j], afh, bh2);
                mma_bf16(oacc[j], afh, bl2);
                mma_bf16(oacc[j], afl, bh2);
            }
        }
        __syncthreads();

        float* stg = (float*)Tc;
        int r0 = m0r + (lane >> 2), r1 = r0 + 8;
        float s0 = rsum[r0], s1 = rsum[r1];
        int fx0 = r0 >> 3, fyl0 = r0 & 7;
        int fx1 = r1 >> 3, fyl1 = r1 & 7;
#pragma unroll
        for (int j = 0; j < 8; j++) {
            int cd = j * 8 + ((lane & 3) << 1);
            int hl = cd >> 4, ww = cd & 15;
            stg[(hl * 8 + fyl0) * 260 + ww * 16 + fx0]       = oacc[j][0] * s0;
            stg[(hl * 8 + fyl0) * 260 + (ww + 1) * 16 + fx0] = oacc[j][1] * s0;
            stg[(hl * 8 + fyl1) * 260 + ww * 16 + fx1]       = oacc[j][2] * s1;
            stg[(hl * 8 + fyl1) * 260 + (ww + 1) * 16 + fx1] = oacc[j][3] * s1;
        }
        __syncthreads();
        int c = ck >> 2, hh0 = (ck & 3) * 4;
#pragma unroll
        for (int rr = 0; rr < 32; rr++) {
            int y = (hh0 + (rr >> 3)) * 16 + fy0 + (rr & 7);
            oimg_base[((size_t)c * 256 + y) * 256 + t] = stg[rr * 260 + t];
        }
        __syncthreads();
    }
}

// ---------------------------------------------------------------------------
// K4: project_out 1x1 conv (R4 scalar version)
// ---------------------------------------------------------------------------
__global__ __launch_bounds__(256) void k_proj(const float* __restrict__ wp,
                                              float* __restrict__ out) {
    __shared__ float ws[48 * 48];
    __shared__ float xs[48 * 64];
    int t = threadIdx.x;
    int b = blockIdx.y;
    int p0 = blockIdx.x * 64;

    for (int i = t; i < 48 * 48; i += 256) ws[i] = wp[i];
    const float* xb = g_oimg + (size_t)b * 48 * HWSZ + p0;
    for (int i = t; i < 48 * 64; i += 256) {
        int c = i >> 6, px = i & 63;
        xs[c * 64 + px] = xb[(size_t)c * HWSZ + px];
    }
    __syncthreads();

    int pxg = t & 15, og = t >> 4;
    float acc[3][4];
#pragma unroll
    for (int j = 0; j < 3; j++)
#pragma unroll
        for (int ii = 0; ii < 4; ii++) acc[j][ii] = 0.f;

#pragma unroll 4
    for (int k = 0; k < 48; k++) {
        float4 xv = *reinterpret_cast<const float4*>(&xs[k * 64 + pxg * 4]);
#pragma unroll
        for (int j = 0; j < 3; j++) {
            float w = ws[(og * 3 + j) * 48 + k];
            acc[j][0] += w * xv.x; acc[j][1] += w * xv.y;
            acc[j][2] += w * xv.z; acc[j][3] += w * xv.w;
        }
    }
    float* ob = out + (size_t)b * 48 * HWSZ + p0 + pxg * 4;
#pragma unroll
    for (int j = 0; j < 3; j++) {
        int o = og * 3 + j;
        float4 v = make_float4(acc[j][0], acc[j][1], acc[j][2], acc[j][3]);
        *reinterpret_cast<float4*>(&ob[(size_t)o * HWSZ]) = v;
    }
}

extern "C" void kernel_launch(void* const* d_in, const int* in_sizes, int n_in,
                              void* d_out, int out_size) {
    const float* x      = (const float*)d_in[0];
    const float* w_qkv  = (const float*)d_in[1];
    const float* w_dw   = (const float*)d_in[2];
    const float* w_proj = (const float*)d_in[3];
    const float* temp   = (const float*)d_in[4];
    float* out = (float*)d_out;

    cudaFuncSetAttribute(k_attn, cudaFuncAttributeMaxDynamicSharedMemorySize, 208 * 1024);

    k_qkv<<<dim3(1024, 8), 256>>>(x, w_qkv);
    k_dw<<<dim3(144, 8, 8), 256>>>(w_dw);
    k_norm<<<4096, 256>>>();
    k_attn<<<dim3(2, 64), 256, 204800>>>(temp);
    k_proj<<<dim3(1024, 8), 256>>>(w_proj, out);
}

// round 8
// speedup vs baseline: 1.9830x; 1.0782x over previous
#include <cuda_runtime.h>
#include <cuda_bf16.h>
#include <cstdint>

#define HWSZ 65536
#define DDIM 1536
#define TOKB_PART (64u*256u*1536u)

__device__ float g_qkv[8u*144u*65536u];
__device__ __nv_bfloat16 g_tokb[3u*TOKB_PART];   // q,k,v(hi) bf16 [part][bh][tok][d]
__device__ __nv_bfloat16 g_vlo[TOKB_PART];       // v residual
__device__ float g_rnorm[2u*16384u];
__device__ float g_oimg[8u*48u*65536u];

__device__ __forceinline__ uint32_t smem_u32(const void* p) {
    uint32_t a;
    asm("{ .reg .u64 t; cvta.to.shared.u64 t, %1; cvt.u32.u64 %0, t; }" : "=r"(a) : "l"(p));
    return a;
}
#define SW128(o) ((o) ^ (((o) >> 3) & 0x70))

__device__ __forceinline__ void ldsm_x4(uint32_t* r, uint32_t a) {
    asm volatile("ldmatrix.sync.aligned.m8n8.x4.shared.b16 {%0,%1,%2,%3}, [%4];"
                 : "=r"(r[0]), "=r"(r[1]), "=r"(r[2]), "=r"(r[3]) : "r"(a));
}
__device__ __forceinline__ void ldsm_x2(uint32_t* r, uint32_t a) {
    asm volatile("ldmatrix.sync.aligned.m8n8.x2.shared.b16 {%0,%1}, [%2];"
                 : "=r"(r[0]), "=r"(r[1]) : "r"(a));
}
__device__ __forceinline__ void ldsm_x2t(uint32_t* r, uint32_t a) {
    asm volatile("ldmatrix.sync.aligned.m8n8.x2.trans.shared.b16 {%0,%1}, [%2];"
                 : "=r"(r[0]), "=r"(r[1]) : "r"(a));
}
__device__ __forceinline__ void mma_bf16(float* c, const uint32_t* a, const uint32_t* b) {
    asm volatile(
        "mma.sync.aligned.m16n8k16.row.col.f32.bf16.bf16.f32 "
        "{%0,%1,%2,%3}, {%4,%5,%6,%7}, {%8,%9}, {%0,%1,%2,%3};"
        : "+f"(c[0]), "+f"(c[1]), "+f"(c[2]), "+f"(c[3])
        : "r"(a[0]), "r"(a[1]), "r"(a[2]), "r"(a[3]), "r"(b[0]), "r"(b[1]));
}
__device__ __forceinline__ void split_hl(float v, __nv_bfloat16& h, __nv_bfloat16& l) {
    h = __float2bfloat16(v);
    l = __float2bfloat16(v - __bfloat162float(h));
}

// ---------------------------------------------------------------------------
// K1 (HMMA v2): qkv 1x1 conv. Block = 128 px x 144 outs, K=48 (3 x k16).
// Coalesced cooperative X load (6 float4/thread), SW128 bf16 hi/lo smem,
// 3-term hi/lo MMA, direct fragment STG (4x32B sectors per warp store).
// smem: Xhi 16K | Xlo 16K | Whi 18K | Wlo 18K = 69632 B.
// ---------------------------------------------------------------------------
__global__ __launch_bounds__(256) void k_qkv(const float* __restrict__ x,
                                             const float* __restrict__ wq) {
    extern __shared__ __align__(128) char smq[];
    char* Xhi = smq;
    char* Xlo = smq + 16384;
    char* Whi = smq + 32768;
    char* Wlo = smq + 51200;

    const int t = threadIdx.x;
    const int warp = t >> 5, lane = t & 31, lm = lane & 15;
    const int b = blockIdx.y;
    const int p0 = blockIdx.x * 128;

    // W -> smem hi/lo ([o][c], K-major rows of 128B)
    for (int i = t; i < 144 * 48; i += 256) {
        int o = i / 48, c = i - o * 48;
        __nv_bfloat16 h, l; split_hl(wq[i], h, l);
        *(__nv_bfloat16*)(Whi + SW128(o * 128 + c * 2)) = h;
        *(__nv_bfloat16*)(Wlo + SW128(o * 128 + c * 2)) = l;
    }
    // X -> smem hi/lo ([px][c]); 48 ch x 32 float4 = 1536 loads, 6 per thread
    const float* xb = x + (size_t)b * 48 * HWSZ + p0;
#pragma unroll
    for (int r = 0; r < 6; r++) {
        int idx = t + 256 * r;
        int c = idx >> 5, f4 = idx & 31;
        float4 v = *reinterpret_cast<const float4*>(&xb[(size_t)c * HWSZ + f4 * 4]);
        int px = f4 * 4;
        __nv_bfloat16 h, l;
        split_hl(v.x, h, l);
        *(__nv_bfloat16*)(Xhi + SW128((px + 0) * 128 + c * 2)) = h;
        *(__nv_bfloat16*)(Xlo + SW128((px + 0) * 128 + c * 2)) = l;
        split_hl(v.y, h, l);
        *(__nv_bfloat16*)(Xhi + SW128((px + 1) * 128 + c * 2)) = h;
        *(__nv_bfloat16*)(Xlo + SW128((px + 1) * 128 + c * 2)) = l;
        split_hl(v.z, h, l);
        *(__nv_bfloat16*)(Xhi + SW128((px + 2) * 128 + c * 2)) = h;
        *(__nv_bfloat16*)(Xlo + SW128((px + 2) * 128 + c * 2)) = l;
        split_hl(v.w, h, l);
        *(__nv_bfloat16*)(Xhi + SW128((px + 3) * 128 + c * 2)) = h;
        *(__nv_bfloat16*)(Xlo + SW128((px + 3) * 128 + c * 2)) = l;
    }
    __syncthreads();

    const int warpM = warp >> 1, warpN = warp & 1;   // 4m x 2n
    const int m0 = warpM * 32, n0 = warpN * 72;
    const uint32_t aXh = smem_u32(Xhi), aXl = smem_u32(Xlo);
    const uint32_t aWh = smem_u32(Whi), aWl = smem_u32(Wlo);

    float acc[2][9][4];
#pragma unroll
    for (int i = 0; i < 2; i++)
#pragma unroll
        for (int j = 0; j < 9; j++)
#pragma unroll
            for (int q = 0; q < 4; q++) acc[i][j][q] = 0.f;

#pragma unroll
    for (int ks = 0; ks < 3; ks++) {
        int k0 = ks * 16;
        uint32_t ah[2][4], al[2][4];
#pragma unroll
        for (int i = 0; i < 2; i++) {
            int row = m0 + i * 16 + lm;
            ldsm_x4(ah[i], aXh + SW128(row * 128 + k0 * 2 + ((lane >> 4) << 4)));
            ldsm_x4(al[i], aXl + SW128(row * 128 + k0 * 2 + ((lane >> 4) << 4)));
        }
        uint32_t bh2[9][2], bl2[9][2];
#pragma unroll
        for (int j = 0; j < 9; j++) {
            int row = n0 + j * 8 + (lm & 7);
            ldsm_x2(bh2[j], aWh + SW128(row * 128 + (k0 + ((lm >> 3) << 3)) * 2));
            ldsm_x2(bl2[j], aWl + SW128(row * 128 + (k0 + ((lm >> 3) << 3)) * 2));
        }
#pragma unroll
        for (int i = 0; i < 2; i++)
#pragma unroll
            for (int j = 0; j < 9; j++) {
                mma_bf16(acc[i][j], ah[i], bh2[j]);
                mma_bf16(acc[i][j], ah[i], bl2[j]);
                mma_bf16(acc[i][j], al[i], bh2[j]);
            }
    }

    // direct fragment stores: per (i,j,q) warp writes 4 o-rows x 8 consec px
    float* outb = g_qkv + (size_t)b * 144 * HWSZ + p0;
#pragma unroll
    for (int i = 0; i < 2; i++) {
        int pxA = m0 + i * 16 + (lane >> 2);
        int pxB = pxA + 8;
#pragma unroll
        for (int j = 0; j < 9; j++) {
            int o = n0 + j * 8 + ((lane & 3) << 1);
            outb[(size_t)o * HWSZ + pxA]       = acc[i][j][0];
            outb[(size_t)(o + 1) * HWSZ + pxA] = acc[i][j][1];
            outb[(size_t)o * HWSZ + pxB]       = acc[i][j][2];
            outb[(size_t)(o + 1) * HWSZ + pxB] = acc[i][j][3];
        }
    }
}

// ---------------------------------------------------------------------------
// K2: depthwise 3x3 via smem row cache (unchanged from R7)
// ---------------------------------------------------------------------------
__global__ __launch_bounds__(256) void k_dw(const float* __restrict__ wdw) {
    __shared__ float rows[34 * 259];
    const int t = threadIdx.x;
    const int ch = blockIdx.x, b = blockIdx.y, z = blockIdx.z;
    const float* src = g_qkv + ((size_t)(b * 144 + ch)) * HWSZ;

    float wd[9];
#pragma unroll
    for (int j = 0; j < 9; j++) wd[j] = wdw[ch * 9 + j];

    const int y0 = z * 32;
    for (int idx = t; idx < 34 * 258; idx += 256) {
        int r = idx / 258, col = idx - r * 258;
        int y = y0 - 1 + r, x = col - 1;
        float v = 0.f;
        if ((unsigned)y < 256u && (unsigned)x < 256u) v = src[y * 256 + x];
        rows[r * 259 + col] = v;
    }
    __syncthreads();

    const int fx = t >> 4, fy = t & 15;
    float ov[2][16];
#pragma unroll
    for (int hl = 0; hl < 2; hl++) {
        const float* r0 = rows + (hl * 16 + fy) * 259 + fx;
        const float* r1 = r0 + 259;
        const float* r2 = r1 + 259;
#pragma unroll
        for (int ww = 0; ww < 16; ww++) {
            int c0 = ww * 16;
            float v = wd[0] * r0[c0] + wd[1] * r0[c0 + 1] + wd[2] * r0[c0 + 2]
                    + wd[3] * r1[c0] + wd[4] * r1[c0 + 1] + wd[5] * r1[c0 + 2]
                    + wd[6] * r2[c0] + wd[7] * r2[c0 + 1] + wd[8] * r2[c0 + 2];
            ov[hl][ww] = v;
        }
    }

    const int part = ch / 48, cc = ch % 48;
    const int head = cc / 6, c = cc % 6;
    const size_t off = (size_t)t * DDIM + c * 256 + z * 32;
    __nv_bfloat16* dst = g_tokb + (size_t)part * TOKB_PART +
                         ((size_t)((b * 8 + head) * 256)) * DDIM + off;
    __nv_bfloat16 hb[32], lb[32];
#pragma unroll
    for (int hl = 0; hl < 2; hl++)
#pragma unroll
        for (int ww = 0; ww < 16; ww++)
            split_hl(ov[hl][ww], hb[hl * 16 + ww], lb[hl * 16 + ww]);
    uint4* d4 = (uint4*)dst;
    d4[0] = ((uint4*)hb)[0]; d4[1] = ((uint4*)hb)[1];
    d4[2] = ((uint4*)hb)[2]; d4[3] = ((uint4*)hb)[3];
    if (part == 2) {
        uint4* l4 = (uint4*)(g_vlo + ((size_t)((b * 8 + head) * 256)) * DDIM + off);
        l4[0] = ((uint4*)lb)[0]; l4[1] = ((uint4*)lb)[1];
        l4[2] = ((uint4*)lb)[2]; l4[3] = ((uint4*)lb)[3];
    }
}

// ---------------------------------------------------------------------------
// K2b: reciprocal L2 norms (unchanged)
// ---------------------------------------------------------------------------
__global__ __launch_bounds__(256) void k_norm() {
    int t = threadIdx.x;
    int w = t >> 5, lane = t & 31;
    int rid = blockIdx.x * 8 + w;
    const __nv_bfloat16* p = g_tokb + (size_t)rid * DDIM;
    float ss = 0.f;
#pragma unroll
    for (int i = 0; i < 48; i++) {
        float v = __bfloat162float(p[lane + 32 * i]);
        ss += v * v;
    }
#pragma unroll
    for (int off = 16; off; off >>= 1) ss += __shfl_xor_sync(0xffffffffu, ss, off);
    if (lane == 0) g_rnorm[rid] = 1.0f / fmaxf(sqrtf(ss), 1e-12f);
}

// ---------------------------------------------------------------------------
// K3: attention (unchanged from R7)
// ---------------------------------------------------------------------------
__global__ __launch_bounds__(256, 1) void k_attn(const float* __restrict__ temperature) {
    extern __shared__ __align__(128) char sm[];
    char* Ahi = sm;
    char* Alo = sm + 67584;
    char* Tc  = sm + 135168;
    float* rqs  = (float*)(sm + 200704);
    float* rks  = rqs + 128;
    float* rsp  = rks + 256;
    float* rsum = rsp + 512;

    const int t = threadIdx.x;
    const int warp = t >> 5, lane = t & 31;
    const int mt = blockIdx.x;
    const int bh = blockIdx.y;
    const int head = bh & 7;
    const int b = bh >> 3;

    const __nv_bfloat16* gq = g_tokb + (size_t)bh * 256 * DDIM;
    const __nv_bfloat16* gk = g_tokb + (size_t)TOKB_PART + (size_t)bh * 256 * DDIM;
    const __nv_bfloat16* gv = g_tokb + 2u * (size_t)TOKB_PART + (size_t)bh * 256 * DDIM;
    const __nv_bfloat16* gvl = g_vlo + (size_t)bh * 256 * DDIM;

    const uint32_t aAh = smem_u32(Ahi);
    const uint32_t aAl = smem_u32(Alo);
    const uint32_t aV  = smem_u32(Tc);
    const uint32_t aK  = aV + 16384;
    const uint32_t aVl = aV + 32768;

    if (t < 128) {
        int n = (t >> 3) * 16 + mt * 8 + (t & 7);
        rqs[t] = g_rnorm[bh * 256 + n] * temperature[head];
    }
    rks[t] = g_rnorm[16384 + bh * 256 + t];

    const int warpM = warp >> 2, warpN = warp & 3;
    float acc[4][8][4];
#pragma unroll
    for (int i = 0; i < 4; i++)
#pragma unroll
        for (int j = 0; j < 8; j++)
#pragma unroll
            for (int q = 0; q < 4; q++) acc[i][j][q] = 0.f;

#pragma unroll 1
    for (int ck = 0; ck < 24; ck++) {
        int d0 = ck * 64;
#pragma unroll
        for (int i = 0; i < 4; i++) {
            int s = t + 256 * i; int r = s >> 3, cs = s & 7;
            int n = (r >> 3) * 16 + mt * 8 + (r & 7);
            uint4 v = *(const uint4*)(gq + (size_t)n * DDIM + d0 + cs * 8);
            *(uint4*)(Tc + SW128(r * 128 + cs * 16)) = v;
        }
#pragma unroll
        for (int i = 0; i < 8; i++) {
            int s = t + 256 * i; int m2 = s >> 3, cs = s & 7;
            uint4 v = *(const uint4*)(gk + (size_t)m2 * DDIM + d0 + cs * 8);
            *(uint4*)(Tc + 16384 + SW128(m2 * 128 + cs * 16)) = v;
        }
        __syncthreads();

        int lm = lane & 15;
#pragma unroll
        for (int kk = 0; kk < 4; kk++) {
            int k0 = kk * 16;
            uint32_t af[4][4];
#pragma unroll
            for (int i = 0; i < 4; i++) {
                int row = warpM * 64 + i * 16 + lm;
                ldsm_x4(af[i], aV + SW128(row * 128 + k0 * 2 + ((lane >> 4) << 4)));
            }
            uint32_t bfg[8][2];
#pragma unroll
            for (int j = 0; j < 8; j++) {
                int row = warpN * 64 + j * 8 + (lm & 7);
                ldsm_x2(bfg[j], aK + SW128(row * 128 + (k0 + ((lm >> 3) << 3)) * 2));
            }
#pragma unroll
            for (int i = 0; i < 4; i++)
#pragma unroll
                for (int j = 0; j < 8; j++) mma_bf16(acc[i][j], af[i], bfg[j]);
        }
        __syncthreads();
    }

#pragma unroll
    for (int i = 0; i < 4; i++) {
        int m0 = warpM * 64 + i * 16 + (lane >> 2);
        int m1 = m0 + 8;
        float q0 = rqs[m0], q1 = rqs[m1];
        float r0 = 0.f, r1 = 0.f;
#pragma unroll
        for (int j = 0; j < 8; j++) {
            int n0 = warpN * 64 + j * 8 + ((lane & 3) << 1);
            float k0v = rks[n0], k1v = rks[n0 + 1];
            float e00 = __expf(acc[i][j][0] * q0 * k0v);
            float e01 = __expf(acc[i][j][1] * q0 * k1v);
            float e10 = __expf(acc[i][j][2] * q1 * k0v);
            float e11 = __expf(acc[i][j][3] * q1 * k1v);
            r0 += e00 + e01; r1 += e10 + e11;
            uint32_t p0, p1;
            asm("cvt.rn.bf16x2.f32 %0, %1, %2;" : "=r"(p0) : "f"(e01), "f"(e00));
            asm("cvt.rn.bf16x2.f32 %0, %1, %2;" : "=r"(p1) : "f"(e11), "f"(e10));
            float h00 = __uint_as_float(p0 << 16),  h01 = __uint_as_float(p0 & 0xFFFF0000u);
            float h10 = __uint_as_float(p1 << 16),  h11 = __uint_as_float(p1 & 0xFFFF0000u);
            uint32_t q0p, q1p;
            asm("cvt.rn.bf16x2.f32 %0, %1, %2;" : "=r"(q0p) : "f"(e01 - h01), "f"(e00 - h00));
            asm("cvt.rn.bf16x2.f32 %0, %1, %2;" : "=r"(q1p) : "f"(e11 - h11), "f"(e10 - h10));
            *(uint32_t*)(Ahi + m0 * 528 + n0 * 2) = p0;
            *(uint32_t*)(Ahi + m1 * 528 + n0 * 2) = p1;
            *(uint32_t*)(Alo + m0 * 528 + n0 * 2) = q0p;
            *(uint32_t*)(Alo + m1 * 528 + n0 * 2) = q1p;
        }
        r0 += __shfl_xor_sync(0xffffffffu, r0, 1);
        r0 += __shfl_xor_sync(0xffffffffu, r0, 2);
        r1 += __shfl_xor_sync(0xffffffffu, r1, 1);
        r1 += __shfl_xor_sync(0xffffffffu, r1, 2);
        if ((lane & 3) == 0) {
            rsp[warpN * 128 + m0] = r0;
            rsp[warpN * 128 + m1] = r1;
        }
    }
    __syncthreads();
    if (t < 128) rsum[t] = 1.0f / (rsp[t] + rsp[128 + t] + rsp[256 + t] + rsp[384 + t] + 1.0f);
    __syncthreads();

    float* oimg_base = g_oimg + ((size_t)(b * 48 + head * 6)) * HWSZ;
    const int fy0 = mt * 8;
    const int lm = lane & 15;
#pragma unroll 1
    for (int ck = 0; ck < 24; ck++) {
        int d0 = ck * 64;
#pragma unroll
        for (int i = 0; i < 8; i++) {
            int s = t + 256 * i; int m2 = s >> 3, cs = s & 7;
            uint4 v = *(const uint4*)(gv + (size_t)m2 * DDIM + d0 + cs * 8);
            *(uint4*)(Tc + SW128(m2 * 128 + cs * 16)) = v;
            uint4 vl = *(const uint4*)(gvl + (size_t)m2 * DDIM + d0 + cs * 8);
            *(uint4*)(Tc + 32768 + SW128(m2 * 128 + cs * 16)) = vl;
        }
        __syncthreads();

        float oacc[8][4];
#pragma unroll
        for (int j = 0; j < 8; j++)
#pragma unroll
            for (int q = 0; q < 4; q++) oacc[j][q] = 0.f;

        int m0r = warp * 16;
#pragma unroll 1
        for (int kk = 0; kk < 16; kk++) {
            int n0 = kk * 16;
            uint32_t afh[4], afl[4];
            ldsm_x4(afh, aAh + (m0r + lm) * 528 + (n0 + ((lane >> 4) << 3)) * 2);
            ldsm_x4(afl, aAl + (m0r + lm) * 528 + (n0 + ((lane >> 4) << 3)) * 2);
#pragma unroll
            for (int j = 0; j < 8; j++) {
                uint32_t bh2[2], bl2[2];
                ldsm_x2t(bh2, aV + SW128((n0 + lm) * 128 + j * 16));
                ldsm_x2t(bl2, aVl + SW128((n0 + lm) * 128 + j * 16));
                mma_bf16(oacc[j], afh, bh2);
                mma_bf16(oacc[j], afh, bl2);
                mma_bf16(oacc[j], afl, bh2);
            }
        }
        __syncthreads();

        float* stg = (float*)Tc;
        int r0 = m0r + (lane >> 2), r1 = r0 + 8;
        float s0 = rsum[r0], s1 = rsum[r1];
        int fx0 = r0 >> 3, fyl0 = r0 & 7;
        int fx1 = r1 >> 3, fyl1 = r1 & 7;
#pragma unroll
        for (int j = 0; j < 8; j++) {
            int cd = j * 8 + ((lane & 3) << 1);
            int hl = cd >> 4, ww = cd & 15;
            stg[(hl * 8 + fyl0) * 260 + ww * 16 + fx0]       = oacc[j][0] * s0;
            stg[(hl * 8 + fyl0) * 260 + (ww + 1) * 16 + fx0] = oacc[j][1] * s0;
            stg[(hl * 8 + fyl1) * 260 + ww * 16 + fx1]       = oacc[j][2] * s1;
            stg[(hl * 8 + fyl1) * 260 + (ww + 1) * 16 + fx1] = oacc[j][3] * s1;
        }
        __syncthreads();
        int c = ck >> 2, hh0 = (ck & 3) * 4;
#pragma unroll
        for (int rr = 0; rr < 32; rr++) {
            int y = (hh0 + (rr >> 3)) * 16 + fy0 + (rr & 7);
            oimg_base[((size_t)c * 256 + y) * 256 + t] = stg[rr * 260 + t];
        }
        __syncthreads();
    }
}

// ---------------------------------------------------------------------------
// K4: project_out 1x1 conv (unchanged scalar)
// ---------------------------------------------------------------------------
__global__ __launch_bounds__(256) void k_proj(const float* __restrict__ wp,
                                              float* __restrict__ out) {
    __shared__ float ws[48 * 48];
    __shared__ float xs[48 * 64];
    int t = threadIdx.x;
    int b = blockIdx.y;
    int p0 = blockIdx.x * 64;

    for (int i = t; i < 48 * 48; i += 256) ws[i] = wp[i];
    const float* xb = g_oimg + (size_t)b * 48 * HWSZ + p0;
    for (int i = t; i < 48 * 64; i += 256) {
        int c = i >> 6, px = i & 63;
        xs[c * 64 + px] = xb[(size_t)c * HWSZ + px];
    }
    __syncthreads();

    int pxg = t & 15, og = t >> 4;
    float acc[3][4];
#pragma unroll
    for (int j = 0; j < 3; j++)
#pragma unroll
        for (int ii = 0; ii < 4; ii++) acc[j][ii] = 0.f;

#pragma unroll 4
    for (int k = 0; k < 48; k++) {
        float4 xv = *reinterpret_cast<const float4*>(&xs[k * 64 + pxg * 4]);
#pragma unroll
        for (int j = 0; j < 3; j++) {
            float w = ws[(og * 3 + j) * 48 + k];
            acc[j][0] += w * xv.x; acc[j][1] += w * xv.y;
            acc[j][2] += w * xv.z; acc[j][3] += w * xv.w;
        }
    }
    float* ob = out + (size_t)b * 48 * HWSZ + p0 + pxg * 4;
#pragma unroll
    for (int j = 0; j < 3; j++) {
        int o = og * 3 + j;
        float4 v = make_float4(acc[j][0], acc[j][1], acc[j][2], acc[j][3]);
        *reinterpret_cast<float4*>(&ob[(size_t)o * HWSZ]) = v;
    }
}

extern "C" void kernel_launch(void* const* d_in, const int* in_sizes, int n_in,
                              void* d_out, int out_size) {
    const float* x      = (const float*)d_in[0];
    const float* w_qkv  = (const float*)d_in[1];
    const float* w_dw   = (const float*)d_in[2];
    const float* w_proj = (const float*)d_in[3];
    const float* temp   = (const float*)d_in[4];
    float* out = (float*)d_out;

    cudaFuncSetAttribute(k_attn, cudaFuncAttributeMaxDynamicSharedMemorySize, 208 * 1024);
    cudaFuncSetAttribute(k_qkv, cudaFuncAttributeMaxDynamicSharedMemorySize, 72 * 1024);

    k_qkv<<<dim3(512, 8), 256, 69632>>>(x, w_qkv);
    k_dw<<<dim3(144, 8, 8), 256>>>(w_dw);
    k_norm<<<4096, 256>>>();
    k_attn<<<dim3(2, 64), 256, 204800>>>(temp);
    k_proj<<<dim3(1024, 8), 256>>>(w_proj, out);
}